// round 4
// baseline (speedup 1.0000x reference)
#include <cuda_runtime.h>

#define NN 100000
#define DIM 64
#define NREL 16
#define EMAX 1000000
#define IDS_CAP (EMAX + NREL * 128)
#define CHUNK 8

__device__ float g_neighbor[NN * DIM];
__device__ int   g_ids[IDS_CAP];
__device__ int   g_cnt[NREL];
__device__ int   g_off[NREL + 1];
__device__ int   g_cursor[NREL];
__device__ int   g_tile_cursor;

// ---------- f32x2 helpers ----------
__device__ __forceinline__ void fma2(unsigned long long& d, unsigned long long a, unsigned long long b) {
    asm("fma.rn.f32x2 %0, %1, %2, %0;" : "+l"(d) : "l"(a), "l"(b));
}
__device__ __forceinline__ float2 unpack2(unsigned long long v) {
    float2 r;
    r.x = __uint_as_float((unsigned)(v & 0xffffffffull));
    r.y = __uint_as_float((unsigned)(v >> 32));
    return r;
}
__device__ __forceinline__ unsigned long long pack2(float x, float y) {
    unsigned long long r;
    asm("mov.b64 %0, {%1, %2};" : "=l"(r) : "f"(x), "f"(y));
    return r;
}
__device__ __forceinline__ float fast_tanh(float x) {
    float e = __expf(2.0f * x);
    return 1.0f - __fdividef(2.0f, e + 1.0f);
}
__device__ __forceinline__ void red_add_v4(float* addr, float a, float b, float c, float d) {
    asm volatile("red.global.add.v4.f32 [%0], {%1, %2, %3, %4};"
                 :: "l"(addr), "f"(a), "f"(b), "f"(c), "f"(d) : "memory");
}

// ---------- launch 0: init + histogram (fused) ----------
__global__ __launch_bounds__(256) void init_hist_kernel(const int* __restrict__ etype,
                                                        int E, int n4neigh, int n4ids) {
    __shared__ int h[NREL];
    if (threadIdx.x < NREL) h[threadIdx.x] = 0;
    __syncthreads();
    int gtid = blockIdx.x * blockDim.x + threadIdx.x;
    int stride = gridDim.x * blockDim.x;
    if (gtid == 0) g_tile_cursor = 0;
    if (gtid < NREL) g_cnt[gtid] = 0;
    for (int i = gtid; i < n4neigh; i += stride)
        ((float4*)g_neighbor)[i] = make_float4(0.f, 0.f, 0.f, 0.f);
    for (int i = gtid; i < n4ids; i += stride)
        ((int4*)g_ids)[i] = make_int4(-1, -1, -1, -1);
    for (int i = gtid; i < E; i += stride)
        atomicAdd(&h[etype[i]], 1);
    __syncthreads();
    if (threadIdx.x < NREL) atomicAdd(&g_cnt[threadIdx.x], h[threadIdx.x]);
}

// ---------- launch 1: 128-aligned prefix ----------
__global__ void prefix_kernel() {
    if (threadIdx.x == 0) {
        int acc = 0;
        for (int r = 0; r < NREL; r++) {
            g_off[r] = acc;
            g_cursor[r] = acc;
            acc += (g_cnt[r] + 127) & ~127;
        }
        g_off[NREL] = acc;
    }
}

// ---------- launch 2: scatter edge ids into relation-sorted array ----------
__global__ __launch_bounds__(256) void scatter_kernel(const int* __restrict__ etype, int E) {
    __shared__ int cnt[NREL], base[NREL];
    const int CH = 4096;
    int e0 = blockIdx.x * CH;
    if (threadIdx.x < NREL) cnt[threadIdx.x] = 0;
    __syncthreads();
    for (int i = threadIdx.x; i < CH; i += 256) {
        int e = e0 + i;
        if (e < E) atomicAdd(&cnt[etype[e]], 1);
    }
    __syncthreads();
    if (threadIdx.x < NREL) {
        base[threadIdx.x] = atomicAdd(&g_cursor[threadIdx.x], cnt[threadIdx.x]);
        cnt[threadIdx.x] = 0;
    }
    __syncthreads();
    for (int i = threadIdx.x; i < CH; i += 256) {
        int e = e0 + i;
        if (e < E) {
            int r = etype[e];
            int p = base[r] + atomicAdd(&cnt[r], 1);
            g_ids[p] = e;
        }
    }
}

// ---------- launch 3: edge GEMM + attention + scatter ----------
// 256 threads, tile = 128 edges x 64 cols, 8 rows x 4 cols per thread (f32x2).
// Dynamic tile chunks via global cursor; W_R reloaded only on relation change.
__global__ __launch_bounds__(256, 3) void edge_kernel(
    const float* __restrict__ entity, const float* __restrict__ rel,
    const float* __restrict__ W_R,
    const int* __restrict__ src, const int* __restrict__ dst)
{
    extern __shared__ float sm[];
    float* sW2   = sm;                    // 64 x 128 duplicated W (8192)
    float* sX    = sW2 + 8192;            // transposed X [k=64][row=128] (8192)
    float* sRe   = sX + 8192;             // 64
    float* sAttP = sRe + 64;              // [128][17] = 2176
    int*   sOff  = (int*)(sAttP + 2176);  // 17 (+pad)
    int*   sIds  = sOff + 18;             // 128
    int*   sTile = sIds + 128;            // 1

    const int tid = threadIdx.x;
    if (tid < NREL + 1) sOff[tid] = g_off[tid];
    __syncthreads();
    const int tiles_total = sOff[NREL] >> 7;

    const int row  = tid >> 1;        // gather/scatter row 0..127
    const int half = tid & 1;         // half-row 0/1
    const int ti = tid & 15;          // GEMM rows ti*8..ti*8+7
    const int tj = tid >> 4;          // GEMM cols tj*4..tj*4+3

    int r_cur = -1;

    for (;;) {
        __syncthreads();              // protect sTile + smem reuse
        if (tid == 0) sTile[0] = atomicAdd(&g_tile_cursor, CHUNK);
        __syncthreads();
        int t0 = sTile[0];
        if (t0 >= tiles_total) break;
        int t1 = min(t0 + CHUNK, tiles_total);

        for (int t = t0; t < t1; t++) {
            const int p0 = t << 7;
            int r = 0;
            while (p0 >= sOff[r + 1]) r++;

            __syncthreads();          // prev tile consumers done with sX/sAttP/sW2
            if (r != r_cur) {
                r_cur = r;
                const float4* wr4 = (const float4*)(W_R + (size_t)r * 4096);
                for (int i = tid; i < 1024; i += 256) {
                    float4 w = wr4[i];
                    int k  = i >> 4;
                    int c4 = i & 15;
                    float* b = sW2 + k * 128 + c4 * 8;
                    *(float4*)(b)     = make_float4(w.x, w.x, w.y, w.y);
                    *(float4*)(b + 4) = make_float4(w.z, w.z, w.w, w.w);
                }
                if (tid < 16) ((float4*)sRe)[tid] = ((const float4*)(rel + r * 64))[tid];
            }

            // ---- gather: thread pair loads one edge row (32 floats each) ----
            const int id = g_ids[p0 + row];
            if (half == 0) sIds[row] = id;
            if (id >= 0) {
                const float4* xp = (const float4*)(entity + (size_t)src[id] * DIM + half * 32);
                #pragma unroll
                for (int q = 0; q < 8; q++) {
                    float4 v = xp[q];
                    int kk = half * 32 + 4 * q;
                    sX[(kk + 0) * 128 + row] = v.x;
                    sX[(kk + 1) * 128 + row] = v.y;
                    sX[(kk + 2) * 128 + row] = v.z;
                    sX[(kk + 3) * 128 + row] = v.w;
                }
            } else {
                #pragma unroll
                for (int kk = 0; kk < 32; kk++)
                    sX[(half * 32 + kk) * 128 + row] = 0.f;
            }
            __syncthreads();

            // ---- GEMM 128x64x64: 8 rows x 4 cols per thread ----
            unsigned long long acc[4][4];
            #pragma unroll
            for (int p = 0; p < 4; p++)
                #pragma unroll
                for (int c = 0; c < 4; c++) acc[p][c] = 0ull;

            const float* xb = sX  + ti * 8;
            const float* wb = sW2 + tj * 8;
            #pragma unroll 8
            for (int k = 0; k < 64; k++) {
                ulonglong2 a01 = *(const ulonglong2*)(xb + k * 128);
                ulonglong2 a23 = *(const ulonglong2*)(xb + k * 128 + 4);
                ulonglong2 b01 = *(const ulonglong2*)(wb + k * 128);
                unsigned long long A[4] = { a01.x, a01.y, a23.x, a23.y };
                unsigned long long B0 = b01.x, B1 = b01.y;
                ulonglong2 b23 = *(const ulonglong2*)(wb + k * 128 + 4);
                unsigned long long B2 = b23.x, B3 = b23.y;
                #pragma unroll
                for (int p = 0; p < 4; p++) {
                    fma2(acc[p][0], A[p], B0);
                    fma2(acc[p][1], A[p], B1);
                    fma2(acc[p][2], A[p], B2);
                    fma2(acc[p][3], A[p], B3);
                }
            }

            // ---- attention partials ----
            float rec[4];
            #pragma unroll
            for (int c = 0; c < 4; c++) rec[c] = sRe[tj * 4 + c];
            float part[8];
            #pragma unroll
            for (int i = 0; i < 8; i++) part[i] = 0.f;
            #pragma unroll
            for (int p = 0; p < 4; p++) {
                #pragma unroll
                for (int c = 0; c < 4; c++) {
                    float2 m = unpack2(acc[p][c]);
                    part[2 * p + 0] += m.x * fast_tanh(m.x + rec[c]);
                    part[2 * p + 1] += m.y * fast_tanh(m.y + rec[c]);
                }
            }
            #pragma unroll
            for (int i = 0; i < 8; i++) sAttP[(ti * 8 + i) * 17 + tj] = part[i];
            __syncthreads();

            // ---- reduce att + scatter half-row per thread ----
            const int id2 = sIds[row];
            if (id2 >= 0) {
                float att = 0.f;
                #pragma unroll
                for (int c = 0; c < 16; c++) att += sAttP[row * 17 + c];
                const float4* xp = (const float4*)(entity + (size_t)src[id2] * DIM + half * 32);
                float* np = g_neighbor + (size_t)dst[id2] * DIM + half * 32;
                #pragma unroll
                for (int q = 0; q < 8; q++) {
                    float4 v = xp[q];
                    red_add_v4(np + 4 * q, att * v.x, att * v.y, att * v.z, att * v.w);
                }
            }
        }
    }
}

// ---------- launch 4: combine out = leaky_relu([h;nb] @ W_w^T + b) + h ----------
__global__ __launch_bounds__(128, 1) void combine_kernel(
    const float* __restrict__ entity, const float* __restrict__ W_w,
    const float* __restrict__ W_b, float* __restrict__ out, int n_nodes)
{
    extern __shared__ float smem[];
    float* sW = smem;                  // transposed W: [k=128][j stride 68] = 8704
    float* sX = sW + 8704;             // transposed X: [k=128][row pad 132] = 16896
    float* sB = sX + 128 * 132;        // 64

    const int tid = threadIdx.x;
    const int n0  = blockIdx.x * 128;

    for (int i = tid; i < 8192; i += 128) {
        int j = i >> 7, k = i & 127;
        sW[k * 68 + j] = W_w[i];
    }
    if (tid < 64) sB[tid] = W_b[tid];

    {
        int n = n0 + tid;
        if (n < n_nodes) {
            const float4* hp = (const float4*)(entity + (size_t)n * DIM);
            const float4* np = (const float4*)(g_neighbor + (size_t)n * DIM);
            #pragma unroll
            for (int q = 0; q < 16; q++) {
                float4 v = hp[q];
                sX[(4 * q + 0) * 132 + tid] = v.x;
                sX[(4 * q + 1) * 132 + tid] = v.y;
                sX[(4 * q + 2) * 132 + tid] = v.z;
                sX[(4 * q + 3) * 132 + tid] = v.w;
                float4 w = np[q];
                sX[(64 + 4 * q + 0) * 132 + tid] = w.x;
                sX[(64 + 4 * q + 1) * 132 + tid] = w.y;
                sX[(64 + 4 * q + 2) * 132 + tid] = w.z;
                sX[(64 + 4 * q + 3) * 132 + tid] = w.w;
            }
        }
    }
    __syncthreads();

    const int ti = tid & 15;
    const int tj = tid >> 4;

    unsigned long long acc[4][8];
    #pragma unroll
    for (int p = 0; p < 4; p++)
        #pragma unroll
        for (int c = 0; c < 8; c++) acc[p][c] = 0ull;

    const float* xb = sX + ti * 8;
    const float* wb = sW + tj * 8;
    #pragma unroll 8
    for (int k = 0; k < 128; k++) {
        float4 a0 = *(const float4*)(xb + k * 132);
        float4 a1 = *(const float4*)(xb + k * 132 + 4);
        float4 w0 = *(const float4*)(wb + k * 68);
        float4 w1 = *(const float4*)(wb + k * 68 + 4);
        unsigned long long A[4] = { pack2(a0.x, a0.y), pack2(a0.z, a0.w),
                                    pack2(a1.x, a1.y), pack2(a1.z, a1.w) };
        unsigned long long B[8] = { pack2(w0.x, w0.x), pack2(w0.y, w0.y),
                                    pack2(w0.z, w0.z), pack2(w0.w, w0.w),
                                    pack2(w1.x, w1.x), pack2(w1.y, w1.y),
                                    pack2(w1.z, w1.z), pack2(w1.w, w1.w) };
        #pragma unroll
        for (int p = 0; p < 4; p++)
            #pragma unroll
            for (int c = 0; c < 8; c++) fma2(acc[p][c], A[p], B[c]);
    }

    float bcol[8];
    #pragma unroll
    for (int c = 0; c < 8; c++) bcol[c] = sB[tj * 8 + c];

    #pragma unroll
    for (int p = 0; p < 4; p++) {
        int r0 = n0 + ti * 8 + 2 * p;
        float v0[8], v1[8];
        #pragma unroll
        for (int c = 0; c < 8; c++) {
            float2 m = unpack2(acc[p][c]);
            float x0 = m.x + bcol[c];
            float x1 = m.y + bcol[c];
            v0[c] = (x0 > 0.f) ? x0 : 0.01f * x0;
            v1[c] = (x1 > 0.f) ? x1 : 0.01f * x1;
        }
        if (r0 < n_nodes) {
            const float4* hp = (const float4*)(entity + (size_t)r0 * DIM);
            float4 e0 = hp[tj * 2], e1 = hp[tj * 2 + 1];
            float4* op = (float4*)(out + (size_t)r0 * DIM + tj * 8);
            op[0] = make_float4(v0[0] + e0.x, v0[1] + e0.y, v0[2] + e0.z, v0[3] + e0.w);
            op[1] = make_float4(v0[4] + e1.x, v0[5] + e1.y, v0[6] + e1.z, v0[7] + e1.w);
        }
        if (r0 + 1 < n_nodes) {
            const float4* hp = (const float4*)(entity + (size_t)(r0 + 1) * DIM);
            float4 e0 = hp[tj * 2], e1 = hp[tj * 2 + 1];
            float4* op = (float4*)(out + (size_t)(r0 + 1) * DIM + tj * 8);
            op[0] = make_float4(v1[0] + e0.x, v1[1] + e0.y, v1[2] + e0.z, v1[3] + e0.w);
            op[1] = make_float4(v1[4] + e1.x, v1[5] + e1.y, v1[6] + e1.z, v1[7] + e1.w);
        }
    }
}

extern "C" void kernel_launch(void* const* d_in, const int* in_sizes, int n_in,
                              void* d_out, int out_size)
{
    const float* entity = (const float*)d_in[0];
    const float* rel    = (const float*)d_in[1];
    const float* W_R    = (const float*)d_in[2];
    const float* W_w    = (const float*)d_in[3];
    const float* W_b    = (const float*)d_in[4];
    const int*   src    = (const int*)d_in[5];
    const int*   dst    = (const int*)d_in[6];
    const int*   etype  = (const int*)d_in[7];

    const int E = in_sizes[5];
    const int n = in_sizes[0] / DIM;

    const size_t smem_edge = (8192 + 8192 + 64 + 2176) * sizeof(float) + (18 + 128 + 2) * sizeof(int);
    const size_t smem_comb = (8704 + 128 * 132 + 64) * sizeof(float);
    cudaFuncSetAttribute(edge_kernel, cudaFuncAttributeMaxDynamicSharedMemorySize, (int)smem_edge);
    cudaFuncSetAttribute(combine_kernel, cudaFuncAttributeMaxDynamicSharedMemorySize, (int)smem_comb);

    int n4neigh = n * DIM / 4;
    int n4ids   = IDS_CAP / 4;

    init_hist_kernel<<<1024, 256>>>(etype, E, n4neigh, n4ids);     // launch 0
    prefix_kernel<<<1, 32>>>();                                    // launch 1
    scatter_kernel<<<(E + 4095) / 4096, 256>>>(etype, E);          // launch 2
    edge_kernel<<<444, 256, smem_edge>>>(entity, rel, W_R, src, dst);  // launch 3 (profiled)
    combine_kernel<<<(n + 127) / 128, 128, smem_comb>>>(entity, W_w, W_b, (float*)d_out, n);  // launch 4
}

// round 5
// speedup vs baseline: 1.3203x; 1.3203x over previous
#include <cuda_runtime.h>

#define NN 100000
#define DIM 64
#define NREL 16
#define EMAX 1000000
#define TM 256                         // edges per tile
#define IDS_CAP (EMAX + NREL * TM)
#define CHUNK 4

__device__ float g_neighbor[NN * DIM];
__device__ int   g_ids[IDS_CAP];
__device__ int   g_cnt[NREL];
__device__ int   g_off[NREL + 1];
__device__ int   g_cursor[NREL];
__device__ int   g_tile_cursor;

// ---------- f32x2 helpers ----------
__device__ __forceinline__ void fma2(unsigned long long& d, unsigned long long a, unsigned long long b) {
    asm("fma.rn.f32x2 %0, %1, %2, %0;" : "+l"(d) : "l"(a), "l"(b));
}
__device__ __forceinline__ float2 unpack2(unsigned long long v) {
    float2 r;
    r.x = __uint_as_float((unsigned)(v & 0xffffffffull));
    r.y = __uint_as_float((unsigned)(v >> 32));
    return r;
}
__device__ __forceinline__ unsigned long long pack2(float x, float y) {
    unsigned long long r;
    asm("mov.b64 %0, {%1, %2};" : "=l"(r) : "f"(x), "f"(y));
    return r;
}
__device__ __forceinline__ float fast_tanh(float x) {
    float e = __expf(2.0f * x);
    return 1.0f - __fdividef(2.0f, e + 1.0f);
}
__device__ __forceinline__ void red_add_v4(float* addr, float a, float b, float c, float d) {
    asm volatile("red.global.add.v4.f32 [%0], {%1, %2, %3, %4};"
                 :: "l"(addr), "f"(a), "f"(b), "f"(c), "f"(d) : "memory");
}

// ---------- launch 0: init + histogram (fused) ----------
__global__ __launch_bounds__(256) void init_hist_kernel(const int* __restrict__ etype,
                                                        int E, int n4neigh, int n4ids) {
    __shared__ int h[NREL];
    if (threadIdx.x < NREL) h[threadIdx.x] = 0;
    __syncthreads();
    int gtid = blockIdx.x * blockDim.x + threadIdx.x;
    int stride = gridDim.x * blockDim.x;
    if (gtid == 0) g_tile_cursor = 0;
    if (gtid < NREL) g_cnt[gtid] = 0;
    for (int i = gtid; i < n4neigh; i += stride)
        ((float4*)g_neighbor)[i] = make_float4(0.f, 0.f, 0.f, 0.f);
    for (int i = gtid; i < n4ids; i += stride)
        ((int4*)g_ids)[i] = make_int4(-1, -1, -1, -1);
    for (int i = gtid; i < E; i += stride)
        atomicAdd(&h[etype[i]], 1);
    __syncthreads();
    if (threadIdx.x < NREL) atomicAdd(&g_cnt[threadIdx.x], h[threadIdx.x]);
}

// ---------- launch 1: TM-aligned prefix ----------
__global__ void prefix_kernel() {
    if (threadIdx.x == 0) {
        int acc = 0;
        for (int r = 0; r < NREL; r++) {
            g_off[r] = acc;
            g_cursor[r] = acc;
            acc += (g_cnt[r] + TM - 1) & ~(TM - 1);
        }
        g_off[NREL] = acc;
    }
}

// ---------- launch 2: scatter edge ids into relation-sorted array ----------
__global__ __launch_bounds__(256) void scatter_kernel(const int* __restrict__ etype, int E) {
    __shared__ int cnt[NREL], base[NREL];
    const int CH = 4096;
    int e0 = blockIdx.x * CH;
    if (threadIdx.x < NREL) cnt[threadIdx.x] = 0;
    __syncthreads();
    for (int i = threadIdx.x; i < CH; i += 256) {
        int e = e0 + i;
        if (e < E) atomicAdd(&cnt[etype[e]], 1);
    }
    __syncthreads();
    if (threadIdx.x < NREL) {
        base[threadIdx.x] = atomicAdd(&g_cursor[threadIdx.x], cnt[threadIdx.x]);
        cnt[threadIdx.x] = 0;
    }
    __syncthreads();
    for (int i = threadIdx.x; i < CH; i += 256) {
        int e = e0 + i;
        if (e < E) {
            int r = etype[e];
            int p = base[r] + atomicAdd(&cnt[r], 1);
            g_ids[p] = e;
        }
    }
}

// ---------- launch 3: edge GEMM + attention + scatter ----------
// Tile = 256 edges x 64 cols, 256 threads, 8 rows x 8 cols per thread.
// Col-pair f32x2 accumulators: B = natural adjacent pair from non-dup W (warp-
// uniform broadcast load), A = MOV-duplicated scalar. 2.0 FLOP per smem byte.
__global__ __launch_bounds__(256, 2) void edge_kernel(
    const float* __restrict__ entity, const float* __restrict__ rel,
    const float* __restrict__ W_R,
    const int* __restrict__ src, const int* __restrict__ dst)
{
    extern __shared__ float sm[];
    float* sW    = sm;                    // [k=64][c=64] = 4096
    float* sX    = sW + 4096;             // [k=64][row=256] = 16384
    float* sRe   = sX + 16384;            // 64
    float* sAttP = sRe + 64;              // [256][9] = 2304
    int*   sOff  = (int*)(sAttP + 2304);  // 17 (+pad)
    int*   sIds  = sOff + 18;             // 256
    int*   sTile = sIds + 256;            // 1

    const int tid = threadIdx.x;
    if (tid < NREL + 1) sOff[tid] = g_off[tid];
    __syncthreads();
    const int tiles_total = sOff[NREL] >> 8;

    const int ti = tid & 31;   // rows ti*8 .. ti*8+7
    const int tj = tid >> 5;   // warp id; cols tj*8 .. tj*8+7 (B broadcast per warp)

    int r_cur = -1;

    for (;;) {
        __syncthreads();
        if (tid == 0) sTile[0] = atomicAdd(&g_tile_cursor, CHUNK);
        __syncthreads();
        int t0 = sTile[0];
        if (t0 >= tiles_total) break;
        int t1 = min(t0 + CHUNK, tiles_total);

        for (int t = t0; t < t1; t++) {
            const int p0 = t << 8;
            int r = 0;
            while (p0 >= sOff[r + 1]) r++;

            __syncthreads();          // prev tile consumers done with sX/sAttP/sW
            if (r != r_cur) {
                r_cur = r;
                const float4* wr4 = (const float4*)(W_R + (size_t)r * 4096);
                for (int i = tid; i < 1024; i += 256)
                    ((float4*)sW)[i] = wr4[i];
                if (tid < 16) ((float4*)sRe)[tid] = ((const float4*)(rel + r * 64))[tid];
            }

            // ---- gather: one edge row (64 floats) per thread ----
            const int id = g_ids[p0 + tid];
            sIds[tid] = id;
            if (id >= 0) {
                const float4* xp = (const float4*)(entity + (size_t)src[id] * DIM);
                #pragma unroll
                for (int q = 0; q < 16; q++) {
                    float4 v = xp[q];
                    sX[(4 * q + 0) * 256 + tid] = v.x;
                    sX[(4 * q + 1) * 256 + tid] = v.y;
                    sX[(4 * q + 2) * 256 + tid] = v.z;
                    sX[(4 * q + 3) * 256 + tid] = v.w;
                }
            } else {
                #pragma unroll
                for (int kk = 0; kk < 64; kk++) sX[kk * 256 + tid] = 0.f;
            }
            __syncthreads();

            // ---- GEMM 256x64x64: 8 rows x 8 cols per thread ----
            unsigned long long acc[8][4];
            #pragma unroll
            for (int i = 0; i < 8; i++)
                #pragma unroll
                for (int c = 0; c < 4; c++) acc[i][c] = 0ull;

            const float* xb = sX + ti * 8;
            const float* wb = sW + tj * 8;
            #pragma unroll 4
            for (int k = 0; k < 64; k++) {
                float4 a0 = *(const float4*)(xb + k * 256);
                float4 a1 = *(const float4*)(xb + k * 256 + 4);
                ulonglong2 b01 = *(const ulonglong2*)(wb + k * 64);      // cols 0-3 as 2 pairs
                ulonglong2 b23 = *(const ulonglong2*)(wb + k * 64 + 4);  // cols 4-7
                unsigned long long B0 = b01.x, B1 = b01.y, B2 = b23.x, B3 = b23.y;
                unsigned long long A;
                A = pack2(a0.x, a0.x);
                fma2(acc[0][0], A, B0); fma2(acc[0][1], A, B1); fma2(acc[0][2], A, B2); fma2(acc[0][3], A, B3);
                A = pack2(a0.y, a0.y);
                fma2(acc[1][0], A, B0); fma2(acc[1][1], A, B1); fma2(acc[1][2], A, B2); fma2(acc[1][3], A, B3);
                A = pack2(a0.z, a0.z);
                fma2(acc[2][0], A, B0); fma2(acc[2][1], A, B1); fma2(acc[2][2], A, B2); fma2(acc[2][3], A, B3);
                A = pack2(a0.w, a0.w);
                fma2(acc[3][0], A, B0); fma2(acc[3][1], A, B1); fma2(acc[3][2], A, B2); fma2(acc[3][3], A, B3);
                A = pack2(a1.x, a1.x);
                fma2(acc[4][0], A, B0); fma2(acc[4][1], A, B1); fma2(acc[4][2], A, B2); fma2(acc[4][3], A, B3);
                A = pack2(a1.y, a1.y);
                fma2(acc[5][0], A, B0); fma2(acc[5][1], A, B1); fma2(acc[5][2], A, B2); fma2(acc[5][3], A, B3);
                A = pack2(a1.z, a1.z);
                fma2(acc[6][0], A, B0); fma2(acc[6][1], A, B1); fma2(acc[6][2], A, B2); fma2(acc[6][3], A, B3);
                A = pack2(a1.w, a1.w);
                fma2(acc[7][0], A, B0); fma2(acc[7][1], A, B1); fma2(acc[7][2], A, B2); fma2(acc[7][3], A, B3);
            }

            // ---- attention partials: part[i] = sum_c m*tanh(m + re_c) ----
            float rec[8];
            #pragma unroll
            for (int c = 0; c < 8; c++) rec[c] = sRe[tj * 8 + c];
            #pragma unroll
            for (int i = 0; i < 8; i++) {
                float part = 0.f;
                #pragma unroll
                for (int cp = 0; cp < 4; cp++) {
                    float2 m = unpack2(acc[i][cp]);
                    part += m.x * fast_tanh(m.x + rec[2 * cp + 0]);
                    part += m.y * fast_tanh(m.y + rec[2 * cp + 1]);
                }
                sAttP[(ti * 8 + i) * 9 + tj] = part;
            }
            __syncthreads();

            // ---- reduce att + scatter one row per thread ----
            const int id2 = sIds[tid];
            if (id2 >= 0) {
                float att = 0.f;
                #pragma unroll
                for (int c = 0; c < 8; c++) att += sAttP[tid * 9 + c];
                const float4* xp = (const float4*)(entity + (size_t)src[id2] * DIM);
                float* np = g_neighbor + (size_t)dst[id2] * DIM;
                #pragma unroll
                for (int q = 0; q < 16; q++) {
                    float4 v = xp[q];
                    red_add_v4(np + 4 * q, att * v.x, att * v.y, att * v.z, att * v.w);
                }
            }
        }
    }
}

// ---------- launch 4: combine out = leaky_relu([h;nb] @ W_w^T + b) + h ----------
__global__ __launch_bounds__(128, 1) void combine_kernel(
    const float* __restrict__ entity, const float* __restrict__ W_w,
    const float* __restrict__ W_b, float* __restrict__ out, int n_nodes)
{
    extern __shared__ float smem[];
    float* sW = smem;                  // transposed W: [k=128][j stride 68] = 8704
    float* sX = sW + 8704;             // transposed X: [k=128][row pad 132] = 16896
    float* sB = sX + 128 * 132;        // 64

    const int tid = threadIdx.x;
    const int n0  = blockIdx.x * 128;

    for (int i = tid; i < 8192; i += 128) {
        int j = i >> 7, k = i & 127;
        sW[k * 68 + j] = W_w[i];
    }
    if (tid < 64) sB[tid] = W_b[tid];

    {
        int n = n0 + tid;
        if (n < n_nodes) {
            const float4* hp = (const float4*)(entity + (size_t)n * DIM);
            const float4* np = (const float4*)(g_neighbor + (size_t)n * DIM);
            #pragma unroll
            for (int q = 0; q < 16; q++) {
                float4 v = hp[q];
                sX[(4 * q + 0) * 132 + tid] = v.x;
                sX[(4 * q + 1) * 132 + tid] = v.y;
                sX[(4 * q + 2) * 132 + tid] = v.z;
                sX[(4 * q + 3) * 132 + tid] = v.w;
                float4 w = np[q];
                sX[(64 + 4 * q + 0) * 132 + tid] = w.x;
                sX[(64 + 4 * q + 1) * 132 + tid] = w.y;
                sX[(64 + 4 * q + 2) * 132 + tid] = w.z;
                sX[(64 + 4 * q + 3) * 132 + tid] = w.w;
            }
        }
    }
    __syncthreads();

    const int ti = tid & 15;
    const int tj = tid >> 4;

    unsigned long long acc[4][8];
    #pragma unroll
    for (int p = 0; p < 4; p++)
        #pragma unroll
        for (int c = 0; c < 8; c++) acc[p][c] = 0ull;

    const float* xb = sX + ti * 8;
    const float* wb = sW + tj * 8;
    #pragma unroll 8
    for (int k = 0; k < 128; k++) {
        float4 a0 = *(const float4*)(xb + k * 132);
        float4 a1 = *(const float4*)(xb + k * 132 + 4);
        float4 w0 = *(const float4*)(wb + k * 68);
        float4 w1 = *(const float4*)(wb + k * 68 + 4);
        unsigned long long A[4] = { pack2(a0.x, a0.y), pack2(a0.z, a0.w),
                                    pack2(a1.x, a1.y), pack2(a1.z, a1.w) };
        unsigned long long B[8] = { pack2(w0.x, w0.x), pack2(w0.y, w0.y),
                                    pack2(w0.z, w0.z), pack2(w0.w, w0.w),
                                    pack2(w1.x, w1.x), pack2(w1.y, w1.y),
                                    pack2(w1.z, w1.z), pack2(w1.w, w1.w) };
        #pragma unroll
        for (int p = 0; p < 4; p++)
            #pragma unroll
            for (int c = 0; c < 8; c++) fma2(acc[p][c], A[p], B[c]);
    }

    float bcol[8];
    #pragma unroll
    for (int c = 0; c < 8; c++) bcol[c] = sB[tj * 8 + c];

    #pragma unroll
    for (int p = 0; p < 4; p++) {
        int r0 = n0 + ti * 8 + 2 * p;
        float v0[8], v1[8];
        #pragma unroll
        for (int c = 0; c < 8; c++) {
            float2 m = unpack2(acc[p][c]);
            float x0 = m.x + bcol[c];
            float x1 = m.y + bcol[c];
            v0[c] = (x0 > 0.f) ? x0 : 0.01f * x0;
            v1[c] = (x1 > 0.f) ? x1 : 0.01f * x1;
        }
        if (r0 < n_nodes) {
            const float4* hp = (const float4*)(entity + (size_t)r0 * DIM);
            float4 e0 = hp[tj * 2], e1 = hp[tj * 2 + 1];
            float4* op = (float4*)(out + (size_t)r0 * DIM + tj * 8);
            op[0] = make_float4(v0[0] + e0.x, v0[1] + e0.y, v0[2] + e0.z, v0[3] + e0.w);
            op[1] = make_float4(v0[4] + e1.x, v0[5] + e1.y, v0[6] + e1.z, v0[7] + e1.w);
        }
        if (r0 + 1 < n_nodes) {
            const float4* hp = (const float4*)(entity + (size_t)(r0 + 1) * DIM);
            float4 e0 = hp[tj * 2], e1 = hp[tj * 2 + 1];
            float4* op = (float4*)(out + (size_t)(r0 + 1) * DIM + tj * 8);
            op[0] = make_float4(v1[0] + e0.x, v1[1] + e0.y, v1[2] + e0.z, v1[3] + e0.w);
            op[1] = make_float4(v1[4] + e1.x, v1[5] + e1.y, v1[6] + e1.z, v1[7] + e1.w);
        }
    }
}

extern "C" void kernel_launch(void* const* d_in, const int* in_sizes, int n_in,
                              void* d_out, int out_size)
{
    const float* entity = (const float*)d_in[0];
    const float* rel    = (const float*)d_in[1];
    const float* W_R    = (const float*)d_in[2];
    const float* W_w    = (const float*)d_in[3];
    const float* W_b    = (const float*)d_in[4];
    const int*   src    = (const int*)d_in[5];
    const int*   dst    = (const int*)d_in[6];
    const int*   etype  = (const int*)d_in[7];

    const int E = in_sizes[5];
    const int n = in_sizes[0] / DIM;

    const size_t smem_edge = (4096 + 16384 + 64 + 2304) * sizeof(float)
                             + (18 + 256 + 2) * sizeof(int);
    const size_t smem_comb = (8704 + 128 * 132 + 64) * sizeof(float);
    cudaFuncSetAttribute(edge_kernel, cudaFuncAttributeMaxDynamicSharedMemorySize, (int)smem_edge);
    cudaFuncSetAttribute(combine_kernel, cudaFuncAttributeMaxDynamicSharedMemorySize, (int)smem_comb);

    int n4neigh = n * DIM / 4;
    int n4ids   = IDS_CAP / 4;

    init_hist_kernel<<<1024, 256>>>(etype, E, n4neigh, n4ids);     // launch 0
    prefix_kernel<<<1, 32>>>();                                    // launch 1
    scatter_kernel<<<(E + 4095) / 4096, 256>>>(etype, E);          // launch 2
    edge_kernel<<<296, 256, smem_edge>>>(entity, rel, W_R, src, dst);  // launch 3 (profiled)
    combine_kernel<<<(n + 127) / 128, 128, smem_comb>>>(entity, W_w, W_b, (float*)d_out, n);  // launch 4
}